// round 16
// baseline (speedup 1.0000x reference)
#include <cuda_runtime.h>
#include <cstdint>

#define BSZ   8
#define QROWS 12544
#define DD    512
#define LL    77
#define LPAD  80
#define HH    4
#define DH    128
#define NW1   320            // padded score width (4 heads x 80)
#define WB    (DD * NW1)     // 163840 words per batch for W1/U2

static __device__ float g_tn  [616 * 512];
static __device__ float g_K   [616 * 512];
static __device__ float g_V   [616 * 512];
static __device__ float g_W1  [BSZ * WB];    // lane-major B-frag layout [k8][lane][nf][2]
static __device__ float g_U2  [BSZ * WB];    // lane-major B-frag layout [k8][lane][nf][2]
static __device__ float g_bias[BSZ * LPAD];  // 0 or -inf per (b, l%80)

typedef unsigned int uint;

__device__ __forceinline__ float to_tf32(float x) {
    uint u; asm("cvt.rna.tf32.f32 %0, %1;" : "=r"(u) : "f"(x));
    return __uint_as_float(u);
}

__device__ __forceinline__ void mma_tf32(float* d, const uint4& a, uint b0, uint b1) {
    asm volatile(
        "mma.sync.aligned.m16n8k8.row.col.f32.tf32.tf32.f32 "
        "{%0,%1,%2,%3}, {%4,%5,%6,%7}, {%8,%9}, {%0,%1,%2,%3};"
        : "+f"(d[0]), "+f"(d[1]), "+f"(d[2]), "+f"(d[3])
        : "r"(a.x), "r"(a.y), "r"(a.z), "r"(a.w), "r"(b0), "r"(b1));
}

__device__ __forceinline__ void cpasync16(uint saddr, const void* gaddr) {
    asm volatile("cp.async.cg.shared.global [%0], [%1], 16;"
                 :: "r"(saddr), "l"(gaddr));
}
#define CP_COMMIT() asm volatile("cp.async.commit_group;")
#define CP_WAIT1()  asm volatile("cp.async.wait_group 1;")
#define CP_WAIT0()  asm volatile("cp.async.wait_group 0;")

// ---------------------------------------------------------------------------
// Mask normalization with dtype auto-detection (uint8 / int32 / float32).
// ---------------------------------------------------------------------------
__global__ void mask_kernel(const unsigned char* __restrict__ mraw) {
    __shared__ int mode;
    if (threadIdx.x == 0) {
        const uint* w = (const uint*)mraw;
        int all01 = 1, allf = 1;
        for (int i = 0; i < 154; i++) {          // 154*4 = 616 bytes
            uint v = w[i];
            if (v > 1u) all01 = 0;
            if (v != 0u && v != 0x3F800000u) allf = 0;
        }
        mode = all01 ? 1 : (allf ? 2 : 0);
    }
    __syncthreads();
    int m = mode;
    for (int i = threadIdx.x; i < BSZ * LPAD; i += blockDim.x) {
        int bb = i / LPAD, l = i % LPAD;
        int on = 0;
        if (l < LL) {
            int e = bb * LL + l;
            if (m == 1)      on = ((const int*)mraw)[e] != 0;
            else if (m == 2) on = ((const float*)mraw)[e] != 0.0f;
            else             on = mraw[e] != 0;
        }
        g_bias[i] = on ? 0.0f : __int_as_float(0xff800000u);
    }
}

// ---------------------------------------------------------------------------
// LayerNorm over 616 rows of text_feat (eps=1e-6, biased variance).
// ---------------------------------------------------------------------------
__global__ void ln_kernel(const float* __restrict__ text,
                          const float* __restrict__ gamma,
                          const float* __restrict__ beta) {
    int row = blockIdx.x;
    int t   = threadIdx.x;            // 128 threads, 4 elems each
    const float4 v = ((const float4*)(text + (size_t)row * 512))[t];
    float s = v.x + v.y + v.z + v.w;
    __shared__ float red[4];
    #pragma unroll
    for (int o = 16; o; o >>= 1) s += __shfl_xor_sync(0xffffffffu, s, o);
    if ((t & 31) == 0) red[t >> 5] = s;
    __syncthreads();
    float mean = (red[0] + red[1] + red[2] + red[3]) * (1.0f / 512.0f);
    float dx = v.x - mean, dy = v.y - mean, dz = v.z - mean, dw = v.w - mean;
    float ss = dx * dx + dy * dy + dz * dz + dw * dw;
    #pragma unroll
    for (int o = 16; o; o >>= 1) ss += __shfl_xor_sync(0xffffffffu, ss, o);
    __syncthreads();
    if ((t & 31) == 0) red[t >> 5] = ss;
    __syncthreads();
    float var  = (red[0] + red[1] + red[2] + red[3]) * (1.0f / 512.0f);
    float rstd = rsqrtf(var + 1e-6f);
    const float4 g  = ((const float4*)gamma)[t];
    const float4 bb = ((const float4*)beta)[t];
    float4 o = make_float4(dx * rstd * g.x + bb.x, dy * rstd * g.y + bb.y,
                           dz * rstd * g.z + bb.z, dw * rstd * g.w + bb.w);
    ((float4*)(g_tn + (size_t)row * 512))[t] = o;
}

// ---------------------------------------------------------------------------
// K = tn @ Wk, V = tn @ Wv (blockIdx.z selects). 64x64 tiles, 256 threads.
// ---------------------------------------------------------------------------
__global__ __launch_bounds__(256) void gemm_kv(const float* __restrict__ Wk,
                                               const float* __restrict__ Wv) {
    const float* Bm = blockIdx.z ? Wv : Wk;
    float* C        = blockIdx.z ? g_V : g_K;
    const float* A  = g_tn;
    const int M = 616;
    __shared__ __align__(16) float As[16][68];
    __shared__ __align__(16) float Bs[16][64];
    int tid = threadIdx.x, tx = tid & 15, ty = tid >> 4;
    int bm = blockIdx.y * 64, bn = blockIdx.x * 64;
    float acc[16];
    #pragma unroll
    for (int i = 0; i < 16; i++) acc[i] = 0.0f;
    for (int k0 = 0; k0 < 512; k0 += 16) {
        #pragma unroll
        for (int i = 0; i < 4; i++) {
            int e = i * 256 + tid, m = e >> 4, k = e & 15;
            As[k][m] = (bm + m < M) ? A[(size_t)(bm + m) * 512 + k0 + k] : 0.0f;
        }
        #pragma unroll
        for (int i = 0; i < 4; i++) {
            int e = i * 256 + tid, k = e >> 6, n = e & 63;
            Bs[k][n] = Bm[(size_t)(k0 + k) * 512 + bn + n];
        }
        __syncthreads();
        #pragma unroll
        for (int kk = 0; kk < 16; kk++) {
            float4 a4 = *(const float4*)&As[kk][ty * 4];
            float4 b4 = *(const float4*)&Bs[kk][tx * 4];
            float av[4] = {a4.x, a4.y, a4.z, a4.w};
            float bv[4] = {b4.x, b4.y, b4.z, b4.w};
            #pragma unroll
            for (int i = 0; i < 4; i++)
                #pragma unroll
                for (int j = 0; j < 4; j++)
                    acc[i * 4 + j] = fmaf(av[i], bv[j], acc[i * 4 + j]);
        }
        __syncthreads();
    }
    #pragma unroll
    for (int i = 0; i < 4; i++) {
        int m = bm + ty * 4 + i;
        if (m < M) {
            float4 o = make_float4(acc[i*4], acc[i*4+1], acc[i*4+2], acc[i*4+3]);
            *(float4*)&C[(size_t)m * 512 + bn + tx * 4] = o;
        }
    }
}

// ---------------------------------------------------------------------------
// W1[b][c][n=80h+l] = scale * sum_i Wq[c,128h+i] * K_h[b][l,i], written in
// lane-major B-frag layout: off = (c>>3)*2560 + lane*80 + (n>>3)*2 + ((c&7)>>2)
// with lane = ((n&7)<<2)|(c&3).  grid (8, 1, 32).
// ---------------------------------------------------------------------------
__global__ __launch_bounds__(256) void wtilde(const float* __restrict__ Wq) {
    int z = blockIdx.z, b = z >> 2, h = z & 3;
    int c0 = blockIdx.x * 64;
    __shared__ __align__(16) float As[16][68];
    __shared__ __align__(16) float Bs[16][80];
    int tid = threadIdx.x, tx = tid & 15, ty = tid >> 4;
    float acc[20];
    #pragma unroll
    for (int i = 0; i < 20; i++) acc[i] = 0.0f;
    for (int k0 = 0; k0 < DH; k0 += 16) {
        #pragma unroll
        for (int i = 0; i < 4; i++) {
            int e = i * 256 + tid, m = e >> 4, k = e & 15;
            As[k][m] = Wq[(size_t)(c0 + m) * DD + h * DH + k0 + k];
        }
        #pragma unroll
        for (int i = 0; i < 5; i++) {
            int e = i * 256 + tid, k = e / 80, l = e % 80;
            Bs[k][l] = (l < LL) ? g_K[(size_t)(b * LL + l) * DD + h * DH + k0 + k] : 0.0f;
        }
        __syncthreads();
        #pragma unroll
        for (int kk = 0; kk < 16; kk++) {
            float a[4], bb[5];
            #pragma unroll
            for (int i = 0; i < 4; i++) a[i] = As[kk][ty * 4 + i];
            #pragma unroll
            for (int j = 0; j < 5; j++) bb[j] = Bs[kk][tx * 5 + j];
            #pragma unroll
            for (int i = 0; i < 4; i++)
                #pragma unroll
                for (int j = 0; j < 5; j++)
                    acc[i * 5 + j] = fmaf(a[i], bb[j], acc[i * 5 + j]);
        }
        __syncthreads();
    }
    const float SCALE = 0.08838834764831845f;   // 128^-0.5
    float* Wg = g_W1 + (size_t)b * WB;
    #pragma unroll
    for (int i = 0; i < 4; i++) {
        int c = c0 + ty * 4 + i;
        #pragma unroll
        for (int j = 0; j < 5; j++) {
            int n = h * 80 + tx * 5 + j;
            int lane = ((n & 7) << 2) | (c & 3);
            int idx = (c >> 3) * 2560 + lane * 80 + (n >> 3) * 2 + ((c & 7) >> 2);
            Wg[idx] = to_tf32(acc[i * 5 + j] * SCALE);
        }
    }
}

// ---------------------------------------------------------------------------
// U2[b][l'=80h+l][n] = (V_h[b] @ Wo_h)[l][n], rows 77..79 zero, lane-major
// B-frag layout: off = (lp>>3)*4096 + lane*128 + (n>>3)*2 + ((lp&7)>>2),
// lane = ((n&7)<<2)|(lp&3).  grid (8, 2, 32).
// ---------------------------------------------------------------------------
__global__ __launch_bounds__(256) void gemm_u2(const float* __restrict__ Wo) {
    int z = blockIdx.z, b = z >> 2, h = z & 3;
    const float* A  = g_V + (size_t)b * LL * DD + h * DH;
    const float* Bm = Wo + (size_t)h * DH * DD;
    __shared__ __align__(16) float As[16][68];
    __shared__ __align__(16) float Bs[16][64];
    int tid = threadIdx.x, tx = tid & 15, ty = tid >> 4;
    int bm = blockIdx.y * 64, bn = blockIdx.x * 64;
    float acc[16];
    #pragma unroll
    for (int i = 0; i < 16; i++) acc[i] = 0.0f;
    for (int k0 = 0; k0 < DH; k0 += 16) {
        #pragma unroll
        for (int i = 0; i < 4; i++) {
            int e = i * 256 + tid, m = e >> 4, k = e & 15;
            As[k][m] = (bm + m < LL) ? A[(size_t)(bm + m) * DD + k0 + k] : 0.0f;
        }
        #pragma unroll
        for (int i = 0; i < 4; i++) {
            int e = i * 256 + tid, k = e >> 6, n = e & 63;
            Bs[k][n] = Bm[(size_t)(k0 + k) * DD + bn + n];
        }
        __syncthreads();
        #pragma unroll
        for (int kk = 0; kk < 16; kk++) {
            float4 a4 = *(const float4*)&As[kk][ty * 4];
            float4 b4 = *(const float4*)&Bs[kk][tx * 4];
            float av[4] = {a4.x, a4.y, a4.z, a4.w};
            float bv[4] = {b4.x, b4.y, b4.z, b4.w};
            #pragma unroll
            for (int i = 0; i < 4; i++)
                #pragma unroll
                for (int j = 0; j < 4; j++)
                    acc[i * 4 + j] = fmaf(av[i], bv[j], acc[i * 4 + j]);
        }
        __syncthreads();
    }
    float* Ug = g_U2 + (size_t)b * WB;
    #pragma unroll
    for (int i = 0; i < 4; i++) {
        int m = bm + ty * 4 + i;
        if (m < LPAD) {
            int lp = h * 80 + m;
            #pragma unroll
            for (int j = 0; j < 4; j++) {
                int n = bn + tx * 4 + j;
                int lane = ((n & 7) << 2) | (lp & 3);
                int idx = (lp >> 3) * 4096 + lane * 128 + (n >> 3) * 2 + ((lp & 7) >> 2);
                Ug[idx] = to_tf32(acc[i * 4 + j]);
            }
        }
    }
}

// ---------------------------------------------------------------------------
// Fused kernel, cp.async double-buffered:
//  GEMM1: S(64x320) = X(64x512) @ W1cat ; softmax ; GEMM2: O = P @ U2cat.
// SMEM map (words):
//   [0..12288)      GEMM1 buf0: Xs(2048) + Ws(10240)   /  GEMM2 bufU0 at [0..8192)
//   [12288..24576)  GEMM1 buf1                          /  GEMM2 bufU1 at [8192..16384)
//   [24576..45056)  Ps: [knf40][mf4][lane32][4]
// ---------------------------------------------------------------------------
#define G1_BUF   12288
#define PS_OFF   24576
#define SMEM_WORDS 45056
#define SMEM_BYTES (SMEM_WORDS * 4)

__global__ __launch_bounds__(256) void fused2(const float* __restrict__ X,
                                              float* __restrict__ Out) {
    extern __shared__ __align__(16) float sm[];
    float* Ps = sm + PS_OFF;
    const uint smem_u = (uint)__cvta_generic_to_shared(sm);

    const int b = blockIdx.y, row0 = blockIdx.x * 64;
    const int tid = threadIdx.x, lane = tid & 31, wid = tid >> 5;
    const int wn = wid & 3, wm = wid >> 2;
    const int g = lane >> 2, q = lane & 3;

    // per-thread mask bias: each warp's 10 nfrags span exactly one head, so
    // the head-LOCAL column is nf*8 + q*2  (FIX of R15's `& 79` bug).
    float bs[10][2];
    #pragma unroll
    for (int nf = 0; nf < 10; nf++) {
        int cl = nf * 8 + q * 2;               // 0..78, local within head
        bs[nf][0] = g_bias[b * LPAD + cl];
        bs[nf][1] = g_bias[b * LPAD + cl + 1];
    }

    const float* Xb = X + ((size_t)b * QROWS + row0) * DD;
    const float* Wg = g_W1 + (size_t)b * WB;
    const float* Ug = g_U2 + (size_t)b * WB;

    const int r  = tid >> 2;          // 0..63 staging row
    const int kb = (tid & 3) * 8;     // 0,8,16,24 staging k-base
    const int ksX = kb >> 3, mfX = r >> 4;

    // -------- staging helpers --------
    float xr[8];
#define LDG_X(c) do {                                                        \
        const float4* xp = (const float4*)(Xb + (size_t)r * DD + (c) * 32 + kb); \
        float4 v0 = xp[0], v1 = xp[1];                                       \
        xr[0]=v0.x; xr[1]=v0.y; xr[2]=v0.z; xr[3]=v0.w;                      \
        xr[4]=v1.x; xr[5]=v1.y; xr[6]=v1.z; xr[7]=v1.w;                      \
    } while(0)
#define STS_X(s) do {                                                        \
        float* xd = sm + (s) * G1_BUF;                                       \
        _Pragma("unroll")                                                    \
        for (int j = 0; j < 8; j++) {                                        \
            int kk = kb + j;                                                 \
            int tf = ((r & 7) << 2) | (kk & 3);                              \
            int ai = ((r >> 3) & 1) | (((kk >> 2) & 1) << 1);                \
            xd[((ksX * 4 + mfX) * 32 + tf) * 4 + ai] = to_tf32(xr[j]);       \
        }                                                                    \
    } while(0)
#define CP_W(c, s) do {                                                      \
        const float4* srcp = (const float4*)(Wg + (size_t)(c) * 10240) + tid;\
        uint dstp = smem_u + ((s) * G1_BUF + 2048) * 4 + tid * 16;           \
        _Pragma("unroll")                                                    \
        for (int ii = 0; ii < 10; ii++)                                      \
            cpasync16(dstp + ii * 4096, srcp + ii * 256);                    \
    } while(0)
#define CP_U(c, s) do {                                                      \
        const float4* srcp = (const float4*)(Ug + (size_t)(c) * 8192) + tid; \
        uint dstp = smem_u + (s) * 8192 * 4 + tid * 16;                      \
        _Pragma("unroll")                                                    \
        for (int ii = 0; ii < 8; ii++)                                       \
            cpasync16(dstp + ii * 4096, srcp + ii * 256);                    \
    } while(0)

    // ---------------- GEMM1: 16 chunks of 32 k ----------------
    float acc1[2][10][4];
    #pragma unroll
    for (int mf = 0; mf < 2; mf++)
        #pragma unroll
        for (int nf = 0; nf < 10; nf++)
            #pragma unroll
            for (int c = 0; c < 4; c++) acc1[mf][nf][c] = 0.0f;

    LDG_X(0); CP_W(0, 0); CP_COMMIT();
    STS_X(0);
    LDG_X(1); CP_W(1, 1); CP_COMMIT();

    for (int i = 0; i < 16; i++) {
        const int cur = i & 1;
        if (i < 15) { CP_WAIT1(); } else { CP_WAIT0(); }
        __syncthreads();
        if (i < 15) STS_X(cur ^ 1);          // chunk i+1 X into other buffer
        if (i < 14) LDG_X(i + 2);
        {
            const float* Xs = sm + cur * G1_BUF;
            const float* Ws = sm + cur * G1_BUF + 2048;
            #pragma unroll
            for (int ks = 0; ks < 4; ks++) {
                uint4 a0 = *(const uint4*)&Xs[((ks * 4 + 2 * wm)     * 32 + lane) * 4];
                uint4 a1 = *(const uint4*)&Xs[((ks * 4 + 2 * wm + 1) * 32 + lane) * 4];
                const uint4* bp = (const uint4*)&Ws[((ks * 32 + lane) * 40 + wn * 10) * 2];
                #pragma unroll
                for (int j = 0; j < 5; j++) {
                    uint4 bb = bp[j];
                    mma_tf32(acc1[0][2*j],   a0, bb.x, bb.y);
                    mma_tf32(acc1[1][2*j],   a1, bb.x, bb.y);
                    mma_tf32(acc1[0][2*j+1], a0, bb.z, bb.w);
                    mma_tf32(acc1[1][2*j+1], a1, bb.z, bb.w);
                }
            }
        }
        __syncthreads();
        if (i < 14) { CP_W(i + 2, cur); CP_COMMIT(); }
    }

    // prefetch first two U chunks before softmax (overlaps with exp math)
    CP_U(0, 0); CP_COMMIT();
    CP_U(1, 1); CP_COMMIT();

    // ---------------- softmax + write P into Ps (GEMM2 A-frag layout) ------
    const float NEG = __int_as_float(0xff800000u);
    const int tf0 = (g << 2) | ((2 * q) & 3);
    const int tf1 = (g << 2) | ((2 * q + 1) & 3);
    const int hi4 = (q >= 2) ? 2 : 0;
    #pragma unroll
    for (int mf = 0; mf < 2; mf++) {
        float m0 = NEG, m1 = NEG;
        #pragma unroll
        for (int nf = 0; nf < 10; nf++) {
            acc1[mf][nf][0] += bs[nf][0];  acc1[mf][nf][1] += bs[nf][1];
            acc1[mf][nf][2] += bs[nf][0];  acc1[mf][nf][3] += bs[nf][1];
            m0 = fmaxf(m0, fmaxf(acc1[mf][nf][0], acc1[mf][nf][1]));
            m1 = fmaxf(m1, fmaxf(acc1[mf][nf][2], acc1[mf][nf][3]));
        }
        m0 = fmaxf(m0, __shfl_xor_sync(0xffffffffu, m0, 1));
        m0 = fmaxf(m0, __shfl_xor_sync(0xffffffffu, m0, 2));
        m1 = fmaxf(m1, __shfl_xor_sync(0xffffffffu, m1, 1));
        m1 = fmaxf(m1, __shfl_xor_sync(0xffffffffu, m1, 2));
        float s0 = 0.0f, s1 = 0.0f;
        #pragma unroll
        for (int nf = 0; nf < 10; nf++) {
            acc1[mf][nf][0] = __expf(acc1[mf][nf][0] - m0);
            acc1[mf][nf][1] = __expf(acc1[mf][nf][1] - m0);
            acc1[mf][nf][2] = __expf(acc1[mf][nf][2] - m1);
            acc1[mf][nf][3] = __expf(acc1[mf][nf][3] - m1);
            s0 += acc1[mf][nf][0] + acc1[mf][nf][1];
            s1 += acc1[mf][nf][2] + acc1[mf][nf][3];
        }
        s0 += __shfl_xor_sync(0xffffffffu, s0, 1);
        s0 += __shfl_xor_sync(0xffffffffu, s0, 2);
        s1 += __shfl_xor_sync(0xffffffffu, s1, 1);
        s1 += __shfl_xor_sync(0xffffffffu, s1, 2);
        float i0 = 1.0f / s0, i1 = 1.0f / s1;
        int mfo = 2 * wm + mf;
        #pragma unroll
        for (int nf = 0; nf < 10; nf++) {
            int base = ((wn * 10 + nf) * 4 + mfo) * 128;
            Ps[base + tf0 * 4 + hi4 + 0] = to_tf32(acc1[mf][nf][0] * i0);
            Ps[base + tf1 * 4 + hi4 + 0] = to_tf32(acc1[mf][nf][1] * i0);
            Ps[base + tf0 * 4 + hi4 + 1] = to_tf32(acc1[mf][nf][2] * i1);
            Ps[base + tf1 * 4 + hi4 + 1] = to_tf32(acc1[mf][nf][3] * i1);
        }
    }

    // ---------------- GEMM2: 20 chunks of 16 k ----------------
    float acc2[2][16][4];
    #pragma unroll
    for (int mf = 0; mf < 2; mf++)
        #pragma unroll
        for (int nf = 0; nf < 16; nf++)
            #pragma unroll
            for (int c = 0; c < 4; c++) acc2[mf][nf][c] = 0.0f;

    for (int i = 0; i < 20; i++) {
        const int cur = i & 1;
        if (i < 19) { CP_WAIT1(); } else { CP_WAIT0(); }
        __syncthreads();        // also publishes Ps on i==0
        {
            const float* Us = sm + cur * 8192;
            #pragma unroll
            for (int ks = 0; ks < 2; ks++) {
                int gk = 2 * i + ks;
                uint4 a0 = *(const uint4*)&Ps[((gk * 4 + 2 * wm)     * 32 + lane) * 4];
                uint4 a1 = *(const uint4*)&Ps[((gk * 4 + 2 * wm + 1) * 32 + lane) * 4];
                const uint4* up = (const uint4*)&Us[((ks * 32 + lane) * 64 + wn * 16) * 2];
                #pragma unroll
                for (int j = 0; j < 8; j++) {
                    uint4 uu = up[j];
                    mma_tf32(acc2[0][2*j],   a0, uu.x, uu.y);
                    mma_tf32(acc2[1][2*j],   a1, uu.x, uu.y);
                    mma_tf32(acc2[0][2*j+1], a0, uu.z, uu.w);
                    mma_tf32(acc2[1][2*j+1], a1, uu.z, uu.w);
                }
            }
        }
        __syncthreads();
        if (i < 18) { CP_U(i + 2, cur); CP_COMMIT(); }
    }

    // ---------------- epilogue ----------------
    float* Ob = Out + ((size_t)b * QROWS + row0) * DD;
    #pragma unroll
    for (int mf = 0; mf < 2; mf++) {
        int R = 32 * wm + 16 * mf + g;
        #pragma unroll
        for (int nf = 0; nf < 16; nf++) {
            int col = 128 * wn + nf * 8 + 2 * q;
            *(float2*)&Ob[(size_t)R * DD + col] =
                make_float2(acc2[mf][nf][0], acc2[mf][nf][1]);
            *(float2*)&Ob[(size_t)(R + 8) * DD + col] =
                make_float2(acc2[mf][nf][2], acc2[mf][nf][3]);
        }
    }
#undef LDG_X
#undef STS_X
#undef CP_W
#undef CP_U
}

// ---------------------------------------------------------------------------
extern "C" void kernel_launch(void* const* d_in, const int* in_sizes, int n_in,
                              void* d_out, int out_size) {
    const float*         visual = (const float*)d_in[0];
    const float*         text   = (const float*)d_in[1];
    const unsigned char* mask   = (const unsigned char*)d_in[2];
    const float*         Wq     = (const float*)d_in[3];
    const float*         Wk     = (const float*)d_in[4];
    const float*         Wv     = (const float*)d_in[5];
    const float*         Wo     = (const float*)d_in[6];
    const float*         gamma  = (const float*)d_in[7];
    const float*         beta   = (const float*)d_in[8];
    float* out = (float*)d_out;

    cudaFuncSetAttribute(fused2, cudaFuncAttributeMaxDynamicSharedMemorySize,
                         SMEM_BYTES);

    mask_kernel<<<1, 256>>>(mask);
    ln_kernel<<<616, 128>>>(text, gamma, beta);
    dim3 gkv(8, 10, 2);
    gemm_kv<<<gkv, 256>>>(Wk, Wv);
    dim3 gw(8, 1, 32);
    wtilde<<<gw, 256>>>(Wq);
    dim3 gu(8, 2, 32);
    gemm_u2<<<gu, 256>>>(Wo);
    dim3 gf(QROWS / 64, BSZ);
    fused2<<<gf, 256, SMEM_BYTES>>>(visual, out);
}

// round 17
// speedup vs baseline: 1.9571x; 1.9571x over previous
#include <cuda_runtime.h>
#include <cstdint>

#define BSZ   8
#define QROWS 12544
#define DD    512
#define LL    77
#define LPAD  80
#define HH    4
#define DH    128
#define NW1   320            // padded score width (4 heads x 80)
#define WB    (DD * NW1)     // 163840 words per batch for W1/U2

static __device__ float g_tn  [616 * 512];
static __device__ float g_K   [616 * 512];
static __device__ float g_V   [616 * 512];
static __device__ float g_W1  [BSZ * WB];    // nf-major B-frag layout [k8][nf][lane][2]
static __device__ float g_U2  [BSZ * WB];    // nf-major B-frag layout [k8][nf][lane][2]
static __device__ float g_bias[BSZ * LPAD];  // 0 or -inf per (b, l%80)

typedef unsigned int uint;

__device__ __forceinline__ float to_tf32(float x) {
    uint u; asm("cvt.rna.tf32.f32 %0, %1;" : "=r"(u) : "f"(x));
    return __uint_as_float(u);
}

__device__ __forceinline__ void mma_tf32(float* d, uint a0, uint a1, uint a2, uint a3,
                                         uint b0, uint b1) {
    asm volatile(
        "mma.sync.aligned.m16n8k8.row.col.f32.tf32.tf32.f32 "
        "{%0,%1,%2,%3}, {%4,%5,%6,%7}, {%8,%9}, {%0,%1,%2,%3};"
        : "+f"(d[0]), "+f"(d[1]), "+f"(d[2]), "+f"(d[3])
        : "r"(a0), "r"(a1), "r"(a2), "r"(a3), "r"(b0), "r"(b1));
}

__device__ __forceinline__ void cpasync16(uint saddr, const void* gaddr) {
    asm volatile("cp.async.cg.shared.global [%0], [%1], 16;"
                 :: "r"(saddr), "l"(gaddr));
}
#define CP_COMMIT() asm volatile("cp.async.commit_group;")
#define CP_WAIT1()  asm volatile("cp.async.wait_group 1;")
#define CP_WAIT0()  asm volatile("cp.async.wait_group 0;")

// ---------------------------------------------------------------------------
// Mask normalization with dtype auto-detection (uint8 / int32 / float32).
// ---------------------------------------------------------------------------
__global__ void mask_kernel(const unsigned char* __restrict__ mraw) {
    __shared__ int mode;
    if (threadIdx.x == 0) {
        const uint* w = (const uint*)mraw;
        int all01 = 1, allf = 1;
        for (int i = 0; i < 154; i++) {          // 154*4 = 616 bytes
            uint v = w[i];
            if (v > 1u) all01 = 0;
            if (v != 0u && v != 0x3F800000u) allf = 0;
        }
        mode = all01 ? 1 : (allf ? 2 : 0);
    }
    __syncthreads();
    int m = mode;
    for (int i = threadIdx.x; i < BSZ * LPAD; i += blockDim.x) {
        int bb = i / LPAD, l = i % LPAD;
        int on = 0;
        if (l < LL) {
            int e = bb * LL + l;
            if (m == 1)      on = ((const int*)mraw)[e] != 0;
            else if (m == 2) on = ((const float*)mraw)[e] != 0.0f;
            else             on = mraw[e] != 0;
        }
        g_bias[i] = on ? 0.0f : __int_as_float(0xff800000u);
    }
}

// ---------------------------------------------------------------------------
// LayerNorm over 616 rows of text_feat (eps=1e-6, biased variance).
// ---------------------------------------------------------------------------
__global__ void ln_kernel(const float* __restrict__ text,
                          const float* __restrict__ gamma,
                          const float* __restrict__ beta) {
    int row = blockIdx.x;
    int t   = threadIdx.x;            // 128 threads, 4 elems each
    const float4 v = ((const float4*)(text + (size_t)row * 512))[t];
    float s = v.x + v.y + v.z + v.w;
    __shared__ float red[4];
    #pragma unroll
    for (int o = 16; o; o >>= 1) s += __shfl_xor_sync(0xffffffffu, s, o);
    if ((t & 31) == 0) red[t >> 5] = s;
    __syncthreads();
    float mean = (red[0] + red[1] + red[2] + red[3]) * (1.0f / 512.0f);
    float dx = v.x - mean, dy = v.y - mean, dz = v.z - mean, dw = v.w - mean;
    float ss = dx * dx + dy * dy + dz * dz + dw * dw;
    #pragma unroll
    for (int o = 16; o; o >>= 1) ss += __shfl_xor_sync(0xffffffffu, ss, o);
    __syncthreads();
    if ((t & 31) == 0) red[t >> 5] = ss;
    __syncthreads();
    float var  = (red[0] + red[1] + red[2] + red[3]) * (1.0f / 512.0f);
    float rstd = rsqrtf(var + 1e-6f);
    const float4 g  = ((const float4*)gamma)[t];
    const float4 bb = ((const float4*)beta)[t];
    float4 o = make_float4(dx * rstd * g.x + bb.x, dy * rstd * g.y + bb.y,
                           dz * rstd * g.z + bb.z, dw * rstd * g.w + bb.w);
    ((float4*)(g_tn + (size_t)row * 512))[t] = o;
}

// ---------------------------------------------------------------------------
// K = tn @ Wk, V = tn @ Wv (blockIdx.z selects). 64x64 tiles, 256 threads.
// ---------------------------------------------------------------------------
__global__ __launch_bounds__(256) void gemm_kv(const float* __restrict__ Wk,
                                               const float* __restrict__ Wv) {
    const float* Bm = blockIdx.z ? Wv : Wk;
    float* C        = blockIdx.z ? g_V : g_K;
    const float* A  = g_tn;
    const int M = 616;
    __shared__ __align__(16) float As[16][68];
    __shared__ __align__(16) float Bs[16][64];
    int tid = threadIdx.x, tx = tid & 15, ty = tid >> 4;
    int bm = blockIdx.y * 64, bn = blockIdx.x * 64;
    float acc[16];
    #pragma unroll
    for (int i = 0; i < 16; i++) acc[i] = 0.0f;
    for (int k0 = 0; k0 < 512; k0 += 16) {
        #pragma unroll
        for (int i = 0; i < 4; i++) {
            int e = i * 256 + tid, m = e >> 4, k = e & 15;
            As[k][m] = (bm + m < M) ? A[(size_t)(bm + m) * 512 + k0 + k] : 0.0f;
        }
        #pragma unroll
        for (int i = 0; i < 4; i++) {
            int e = i * 256 + tid, k = e >> 6, n = e & 63;
            Bs[k][n] = Bm[(size_t)(k0 + k) * 512 + bn + n];
        }
        __syncthreads();
        #pragma unroll
        for (int kk = 0; kk < 16; kk++) {
            float4 a4 = *(const float4*)&As[kk][ty * 4];
            float4 b4 = *(const float4*)&Bs[kk][tx * 4];
            float av[4] = {a4.x, a4.y, a4.z, a4.w};
            float bv[4] = {b4.x, b4.y, b4.z, b4.w};
            #pragma unroll
            for (int i = 0; i < 4; i++)
                #pragma unroll
                for (int j = 0; j < 4; j++)
                    acc[i * 4 + j] = fmaf(av[i], bv[j], acc[i * 4 + j]);
        }
        __syncthreads();
    }
    #pragma unroll
    for (int i = 0; i < 4; i++) {
        int m = bm + ty * 4 + i;
        if (m < M) {
            float4 o = make_float4(acc[i*4], acc[i*4+1], acc[i*4+2], acc[i*4+3]);
            *(float4*)&C[(size_t)m * 512 + bn + tx * 4] = o;
        }
    }
}

// ---------------------------------------------------------------------------
// W1[b][c][n=80h+l] = scale * sum_i Wq[c,128h+i] * K_h[b][l,i], nf-major
// B-frag layout: idx = (c>>3)*2560 + (n>>3)*64 + lane*2 + ((c&7)>>2),
// lane = ((n&7)<<2)|(c&3).  grid (8, 1, 32).
// ---------------------------------------------------------------------------
__global__ __launch_bounds__(256) void wtilde(const float* __restrict__ Wq) {
    int z = blockIdx.z, b = z >> 2, h = z & 3;
    int c0 = blockIdx.x * 64;
    __shared__ __align__(16) float As[16][68];
    __shared__ __align__(16) float Bs[16][80];
    int tid = threadIdx.x, tx = tid & 15, ty = tid >> 4;
    float acc[20];
    #pragma unroll
    for (int i = 0; i < 20; i++) acc[i] = 0.0f;
    for (int k0 = 0; k0 < DH; k0 += 16) {
        #pragma unroll
        for (int i = 0; i < 4; i++) {
            int e = i * 256 + tid, m = e >> 4, k = e & 15;
            As[k][m] = Wq[(size_t)(c0 + m) * DD + h * DH + k0 + k];
        }
        #pragma unroll
        for (int i = 0; i < 5; i++) {
            int e = i * 256 + tid, k = e / 80, l = e % 80;
            Bs[k][l] = (l < LL) ? g_K[(size_t)(b * LL + l) * DD + h * DH + k0 + k] : 0.0f;
        }
        __syncthreads();
        #pragma unroll
        for (int kk = 0; kk < 16; kk++) {
            float a[4], bb[5];
            #pragma unroll
            for (int i = 0; i < 4; i++) a[i] = As[kk][ty * 4 + i];
            #pragma unroll
            for (int j = 0; j < 5; j++) bb[j] = Bs[kk][tx * 5 + j];
            #pragma unroll
            for (int i = 0; i < 4; i++)
                #pragma unroll
                for (int j = 0; j < 5; j++)
                    acc[i * 5 + j] = fmaf(a[i], bb[j], acc[i * 5 + j]);
        }
        __syncthreads();
    }
    const float SCALE = 0.08838834764831845f;   // 128^-0.5
    float* Wg = g_W1 + (size_t)b * WB;
    #pragma unroll
    for (int i = 0; i < 4; i++) {
        int c = c0 + ty * 4 + i;
        #pragma unroll
        for (int j = 0; j < 5; j++) {
            int n = h * 80 + tx * 5 + j;
            int idx = (c >> 3) * 2560 + (n >> 3) * 64
                    + (((n & 7) << 2) | (c & 3)) * 2 + ((c & 7) >> 2);
            Wg[idx] = to_tf32(acc[i * 5 + j] * SCALE);
        }
    }
}

// ---------------------------------------------------------------------------
// U2[b][l'=80h+l][n] = (V_h[b] @ Wo_h)[l][n], rows 77..79 zero, nf-major
// B-frag layout: idx = (lp>>3)*4096 + (n>>3)*64 + lane*2 + ((lp&7)>>2),
// lane = ((n&7)<<2)|(lp&3).  grid (8, 2, 32).
// ---------------------------------------------------------------------------
__global__ __launch_bounds__(256) void gemm_u2(const float* __restrict__ Wo) {
    int z = blockIdx.z, b = z >> 2, h = z & 3;
    const float* A  = g_V + (size_t)b * LL * DD + h * DH;
    const float* Bm = Wo + (size_t)h * DH * DD;
    __shared__ __align__(16) float As[16][68];
    __shared__ __align__(16) float Bs[16][64];
    int tid = threadIdx.x, tx = tid & 15, ty = tid >> 4;
    int bm = blockIdx.y * 64, bn = blockIdx.x * 64;
    float acc[16];
    #pragma unroll
    for (int i = 0; i < 16; i++) acc[i] = 0.0f;
    for (int k0 = 0; k0 < DH; k0 += 16) {
        #pragma unroll
        for (int i = 0; i < 4; i++) {
            int e = i * 256 + tid, m = e >> 4, k = e & 15;
            As[k][m] = (bm + m < LL) ? A[(size_t)(bm + m) * DD + k0 + k] : 0.0f;
        }
        #pragma unroll
        for (int i = 0; i < 4; i++) {
            int e = i * 256 + tid, k = e >> 6, n = e & 63;
            Bs[k][n] = Bm[(size_t)(k0 + k) * DD + bn + n];
        }
        __syncthreads();
        #pragma unroll
        for (int kk = 0; kk < 16; kk++) {
            float4 a4 = *(const float4*)&As[kk][ty * 4];
            float4 b4 = *(const float4*)&Bs[kk][tx * 4];
            float av[4] = {a4.x, a4.y, a4.z, a4.w};
            float bv[4] = {b4.x, b4.y, b4.z, b4.w};
            #pragma unroll
            for (int i = 0; i < 4; i++)
                #pragma unroll
                for (int j = 0; j < 4; j++)
                    acc[i * 4 + j] = fmaf(av[i], bv[j], acc[i * 4 + j]);
        }
        __syncthreads();
    }
    float* Ug = g_U2 + (size_t)b * WB;
    #pragma unroll
    for (int i = 0; i < 4; i++) {
        int m = bm + ty * 4 + i;
        if (m < LPAD) {
            int lp = h * 80 + m;
            #pragma unroll
            for (int j = 0; j < 4; j++) {
                int n = bn + tx * 4 + j;
                int idx = (lp >> 3) * 4096 + (n >> 3) * 64
                        + (((n & 7) << 2) | (lp & 3)) * 2 + ((lp & 7) >> 2);
                Ug[idx] = to_tf32(acc[i * 4 + j]);
            }
        }
    }
}

// ---------------------------------------------------------------------------
// Fused kernel, triple-buffered cp.async, one barrier per chunk:
//  GEMM1: S(64x320) = X(64x512) @ W1cat ; softmax ; GEMM2: O = P @ U2cat.
// SMEM (words): 3 GEMM1 bufs of 12304 (Xs 2064 padded + Ws 10240) at s*12304;
//               GEMM2 U bufs overlay at 0/8192/16384; Ps at 36912 (20480).
// ---------------------------------------------------------------------------
#define G1_BUF   12304
#define XS_PAD   516
#define PS_OFF   36912
#define SMEM_WORDS 57392
#define SMEM_BYTES (SMEM_WORDS * 4)   // 229568 <= 232448

__global__ __launch_bounds__(256) void fused2(const float* __restrict__ X,
                                              float* __restrict__ Out) {
    extern __shared__ __align__(16) float sm[];
    float* Ps = sm + PS_OFF;
    const uint smem_u = (uint)__cvta_generic_to_shared(sm);

    const int b = blockIdx.y, row0 = blockIdx.x * 64;
    const int tid = threadIdx.x, lane = tid & 31, wid = tid >> 5;
    const int wn = wid & 3, wm = wid >> 2;
    const int g = lane >> 2, q = lane & 3;

    // per-thread mask bias: each warp's 10 nfrags span one head -> local col
    float bs[10][2];
    #pragma unroll
    for (int nf = 0; nf < 10; nf++) {
        int cl = nf * 8 + q * 2;
        bs[nf][0] = g_bias[b * LPAD + cl];
        bs[nf][1] = g_bias[b * LPAD + cl + 1];
    }

    const float* Xb = X + ((size_t)b * QROWS + row0) * DD;
    const float* Wg = g_W1 + (size_t)b * WB;
    const float* Ug = g_U2 + (size_t)b * WB;

    const int r  = tid >> 2;          // 0..63 staging row
    const int kb = (tid & 3) * 8;     // 0,8,16,24 staging k-base

    float xr[8];
#define LDG_X(c) do {                                                        \
        const float4* xp = (const float4*)(Xb + (size_t)r * DD + (c) * 32 + kb); \
        float4 v0 = xp[0], v1 = xp[1];                                       \
        xr[0]=v0.x; xr[1]=v0.y; xr[2]=v0.z; xr[3]=v0.w;                      \
        xr[4]=v1.x; xr[5]=v1.y; xr[6]=v1.z; xr[7]=v1.w;                      \
    } while(0)
    // Xs layout: [ks(4) stride 516][mf(4)*128][tf(32)*4][ai(4)]
    // ai = j2 | (rb<<1)  (k-hi bit in bit0 -> STS.64 pairs; consumer permutes)
#define STS_X(s) do {                                                        \
        float* xd = sm + (s) * G1_BUF + (tid & 3) * XS_PAD + (r >> 4) * 128; \
        int rb2 = ((r >> 3) & 1) * 2;                                        \
        _Pragma("unroll")                                                    \
        for (int jl = 0; jl < 4; jl++) {                                     \
            int tf = ((r & 7) << 2) | jl;                                    \
            *(float2*)&xd[tf * 4 + rb2] =                                    \
                make_float2(to_tf32(xr[jl]), to_tf32(xr[jl + 4]));           \
        }                                                                    \
    } while(0)
#define CP_W(c, s) do {                                                      \
        const float4* srcp = (const float4*)(Wg + (size_t)(c) * 10240) + tid;\
        uint dstp = smem_u + ((s) * G1_BUF + 2064) * 4 + tid * 16;           \
        _Pragma("unroll")                                                    \
        for (int ii = 0; ii < 10; ii++)                                      \
            cpasync16(dstp + ii * 4096, srcp + ii * 256);                    \
    } while(0)
#define CP_U(c, s) do {                                                      \
        const float4* srcp = (const float4*)(Ug + (size_t)(c) * 8192) + tid; \
        uint dstp = smem_u + (s) * 8192 * 4 + tid * 16;                      \
        _Pragma("unroll")                                                    \
        for (int ii = 0; ii < 8; ii++)                                       \
            cpasync16(dstp + ii * 4096, srcp + ii * 256);                    \
    } while(0)

    // ---------------- GEMM1: 16 chunks of 32 k, depth-2 prefetch ----------
    float acc1[2][10][4];
    #pragma unroll
    for (int mf = 0; mf < 2; mf++)
        #pragma unroll
        for (int nf = 0; nf < 10; nf++)
            #pragma unroll
            for (int c = 0; c < 4; c++) acc1[mf][nf][c] = 0.0f;

    LDG_X(0); STS_X(0); CP_W(0, 0); CP_COMMIT();
    LDG_X(1); STS_X(1); CP_W(1, 1); CP_COMMIT();
    LDG_X(2);

    for (int j = 0; j < 16; j++) {
        const int cur = j % 3;
        if (j < 15) { CP_WAIT1(); } else { CP_WAIT0(); }
        __syncthreads();
        if (j + 2 <= 15) {
            const int nb = (j + 2) % 3;
            STS_X(nb);
            CP_W(j + 2, nb); CP_COMMIT();
        }
        if (j + 3 <= 15) LDG_X(j + 3);
        {
            const float* Xs = sm + cur * G1_BUF;
            const float* Ws = Xs + 2064;
            #pragma unroll
            for (int ks = 0; ks < 4; ks++) {
                uint4 a0 = *(const uint4*)&Xs[ks * XS_PAD + (2 * wm)     * 128 + lane * 4];
                uint4 a1 = *(const uint4*)&Xs[ks * XS_PAD + (2 * wm + 1) * 128 + lane * 4];
                #pragma unroll
                for (int nf = 0; nf < 10; nf++) {
                    uint2 bf = *(const uint2*)&Ws[((ks * 40 + wn * 10 + nf) * 32 + lane) * 2];
                    mma_tf32(acc1[0][nf], a0.x, a0.z, a0.y, a0.w, bf.x, bf.y);
                    mma_tf32(acc1[1][nf], a1.x, a1.z, a1.y, a1.w, bf.x, bf.y);
                }
            }
        }
    }

    // ---------------- softmax + write P into Ps (GEMM2 A-frag layout) ------
    const float NEG = __int_as_float(0xff800000u);
    const int tf0 = (g << 2) | ((2 * q) & 3);
    const int tf1 = (g << 2) | ((2 * q + 1) & 3);
    const int hi4 = (q >= 2) ? 2 : 0;
    #pragma unroll
    for (int mf = 0; mf < 2; mf++) {
        float m0 = NEG, m1 = NEG;
        #pragma unroll
        for (int nf = 0; nf < 10; nf++) {
            acc1[mf][nf][0] += bs[nf][0];  acc1[mf][nf][1] += bs[nf][1];
            acc1[mf][nf][2] += bs[nf][0];  acc1[mf][nf][3] += bs[nf][1];
            m0 = fmaxf(m0, fmaxf(acc1[mf][nf][0], acc1[mf][nf][1]));
            m1 = fmaxf(m1, fmaxf(acc1[mf][nf][2], acc1[mf][nf][3]));
        }
        m0 = fmaxf(m0, __shfl_xor_sync(0xffffffffu, m0, 1));
        m0 = fmaxf(m0, __shfl_xor_sync(0xffffffffu, m0, 2));
        m1 = fmaxf(m1, __shfl_xor_sync(0xffffffffu, m1, 1));
        m1 = fmaxf(m1, __shfl_xor_sync(0xffffffffu, m1, 2));
        float s0 = 0.0f, s1 = 0.0f;
        #pragma unroll
        for (int nf = 0; nf < 10; nf++) {
            acc1[mf][nf][0] = __expf(acc1[mf][nf][0] - m0);
            acc1[mf][nf][1] = __expf(acc1[mf][nf][1] - m0);
            acc1[mf][nf][2] = __expf(acc1[mf][nf][2] - m1);
            acc1[mf][nf][3] = __expf(acc1[mf][nf][3] - m1);
            s0 += acc1[mf][nf][0] + acc1[mf][nf][1];
            s1 += acc1[mf][nf][2] + acc1[mf][nf][3];
        }
        s0 += __shfl_xor_sync(0xffffffffu, s0, 1);
        s0 += __shfl_xor_sync(0xffffffffu, s0, 2);
        s1 += __shfl_xor_sync(0xffffffffu, s1, 1);
        s1 += __shfl_xor_sync(0xffffffffu, s1, 2);
        float i0 = 1.0f / s0, i1 = 1.0f / s1;
        int mfo = 2 * wm + mf;
        #pragma unroll
        for (int nf = 0; nf < 10; nf++) {
            int base = ((wn * 10 + nf) * 4 + mfo) * 128;
            Ps[base + tf0 * 4 + hi4 + 0] = to_tf32(acc1[mf][nf][0] * i0);
            Ps[base + tf1 * 4 + hi4 + 0] = to_tf32(acc1[mf][nf][1] * i0);
            Ps[base + tf0 * 4 + hi4 + 1] = to_tf32(acc1[mf][nf][2] * i1);
            Ps[base + tf1 * 4 + hi4 + 1] = to_tf32(acc1[mf][nf][3] * i1);
        }
    }
    __syncthreads();   // Ps published; all GEMM1 buffer reads complete

    // ---------------- GEMM2: 20 chunks of 16 k, depth-2 prefetch ----------
    float acc2[2][16][4];
    #pragma unroll
    for (int mf = 0; mf < 2; mf++)
        #pragma unroll
        for (int nf = 0; nf < 16; nf++)
            #pragma unroll
            for (int c = 0; c < 4; c++) acc2[mf][nf][c] = 0.0f;

    CP_U(0, 0); CP_COMMIT();
    CP_U(1, 1); CP_COMMIT();

    for (int j = 0; j < 20; j++) {
        const int cur = j % 3;
        if (j < 19) { CP_WAIT1(); } else { CP_WAIT0(); }
        __syncthreads();
        if (j + 2 <= 19) { CP_U(j + 2, (j + 2) % 3); CP_COMMIT(); }
        {
            const float* Us = sm + cur * 8192;
            #pragma unroll
            for (int ks = 0; ks < 2; ks++) {
                int gk = 2 * j + ks;
                uint4 a0 = *(const uint4*)&Ps[((gk * 4 + 2 * wm)     * 32 + lane) * 4];
                uint4 a1 = *(const uint4*)&Ps[((gk * 4 + 2 * wm + 1) * 32 + lane) * 4];
                #pragma unroll
                for (int nf = 0; nf < 16; nf++) {
                    uint2 uu = *(const uint2*)&Us[((ks * 64 + wn * 16 + nf) * 32 + lane) * 2];
                    mma_tf32(acc2[0][nf], a0.x, a0.y, a0.z, a0.w, uu.x, uu.y);
                    mma_tf32(acc2[1][nf], a1.x, a1.y, a1.z, a1.w, uu.x, uu.y);
                }
            }
        }
    }

    // ---------------- epilogue ----------------
    float* Ob = Out + ((size_t)b * QROWS + row0) * DD;
    #pragma unroll
    for (int mf = 0; mf < 2; mf++) {
        int R = 32 * wm + 16 * mf + g;
        #pragma unroll
        for (int nf = 0; nf < 16; nf++) {
            int col = 128 * wn + nf * 8 + 2 * q;
            *(float2*)&Ob[(size_t)R * DD + col] =
                make_float2(acc2[mf][nf][0], acc2[mf][nf][1]);
            *(float2*)&Ob[(size_t)(R + 8) * DD + col] =
                make_float2(acc2[mf][nf][2], acc2[mf][nf][3]);
        }
    }
#undef LDG_X
#undef STS_X
#undef CP_W
#undef CP_U
}

// ---------------------------------------------------------------------------
extern "C" void kernel_launch(void* const* d_in, const int* in_sizes, int n_in,
                              void* d_out, int out_size) {
    const float*         visual = (const float*)d_in[0];
    const float*         text   = (const float*)d_in[1];
    const unsigned char* mask   = (const unsigned char*)d_in[2];
    const float*         Wq     = (const float*)d_in[3];
    const float*         Wk     = (const float*)d_in[4];
    const float*         Wv     = (const float*)d_in[5];
    const float*         Wo     = (const float*)d_in[6];
    const float*         gamma  = (const float*)d_in[7];
    const float*         beta   = (const float*)d_in[8];
    float* out = (float*)d_out;

    cudaFuncSetAttribute(fused2, cudaFuncAttributeMaxDynamicSharedMemorySize,
                         SMEM_BYTES);

    mask_kernel<<<1, 256>>>(mask);
    ln_kernel<<<616, 128>>>(text, gamma, beta);
    dim3 gkv(8, 10, 2);
    gemm_kv<<<gkv, 256>>>(Wk, Wv);
    dim3 gw(8, 1, 32);
    wtilde<<<gw, 256>>>(Wq);
    dim3 gu(8, 2, 32);
    gemm_u2<<<gu, 256>>>(Wo);
    dim3 gf(QROWS / 64, BSZ);
    fused2<<<gf, 256, SMEM_BYTES>>>(visual, out);
}